// round 11
// baseline (speedup 1.0000x reference)
#include <cuda_runtime.h>
#include <math.h>

// Problem constants
#define B_BATCH 4
#define NC_PER  4096     // coarse points per batch
#define NF_TOT  65536
#define K_TOT1  384
#define K_TOT2  256

// ---------------- device scratch (allocation-free contract) ----------------
__device__ float g_xi[(size_t)NF_TOT * 256];      // interpolated feats
__device__ float g_h1[(size_t)NF_TOT * 256];      // post-relu layer1
__device__ int   g_idx[NF_TOT * 3];
__device__ float g_w[NF_TOT * 4];                 // w0,w1,w2, sum
__device__ float g_part[256 * 512];
__device__ float g_mu1[256], g_rsg1[256];
__device__ float g_scale2[256], g_shift2[256];
__device__ int   g_tiecount;
__device__ int   g_tierows[8192];

// d2 = (qq + pp) - 2*((qx*px + qy*py) + qz*pz)  -- asc plain mul/add (XLA
// non-contracted fusion). Must be bit-identical everywhere.
__device__ __forceinline__ float d2_chain(float qx, float qy, float qz, float qq,
                                          float px, float py, float pz, float pp) {
    float dot = __fadd_rn(__fadd_rn(__fmul_rn(qx, px), __fmul_rn(qy, py)),
                          __fmul_rn(qz, pz));
    return __fsub_rn(__fadd_rn(qq, pp), __fmul_rn(2.0f, dot));
}
__device__ __forceinline__ float sq3(float x, float y, float z) {
    return __fadd_rn(__fadd_rn(__fmul_rn(x, x), __fmul_rn(y, y)), __fmul_rn(z, z));
}

__global__ void reset_kernel() { g_tiecount = 0; }

// ---------------- Stage A: fast kNN + boundary-tie flagging ---------------
__global__ void __launch_bounds__(128) knn_kernel(const float* __restrict__ pos,
                                                  const float* __restrict__ pos_skip) {
    __shared__ float4 sp[2048];
    int f = blockIdx.x * 128 + threadIdx.x;
    int b = f >> 14;
    float qx = pos_skip[3 * f + 0];
    float qy = pos_skip[3 * f + 1];
    float qz = pos_skip[3 * f + 2];
    float qq = sq3(qx, qy, qz);
    float d0 = 3.4e38f, d1 = 3.4e38f, d2b = 3.4e38f, v3 = 3.4e38f;
    int i0 = 0, i1 = 0, i2 = 0;
    const float* pb = pos + (size_t)b * NC_PER * 3;

    for (int chunk = 0; chunk < 2; ++chunk) {
        __syncthreads();
        for (int i = threadIdx.x; i < 2048; i += 128) {
            int j = (chunk << 11) + i;
            float px = pb[3 * j + 0], py = pb[3 * j + 1], pz = pb[3 * j + 2];
            sp[i] = make_float4(px, py, pz, sq3(px, py, pz));
        }
        __syncthreads();
        #pragma unroll 4
        for (int i = 0; i < 2048; ++i) {
            float4 p = sp[i];
            float d2 = d2_chain(qx, qy, qz, qq, p.x, p.y, p.z, p.w);
            if (d2 < d2b) {
                int j = (chunk << 11) + i;
                v3 = d2b;
                if (d2 < d1) {
                    d2b = d1; i2 = i1;
                    if (d2 < d0) { d1 = d0; i1 = i0; d0 = d2; i0 = j; }
                    else         { d1 = d2; i1 = j; }
                } else { d2b = d2; i2 = j; }
            } else if (d2 < v3) {
                v3 = d2;    // 4th-smallest value tracker (flag only)
            }
        }
    }
    if (d2b == v3) {        // exact rank-3/4 boundary tie -> exact replay
        int slot = atomicAdd(&g_tiecount, 1);
        if (slot < 8192) g_tierows[slot] = f;
    }
    float w0 = __fdiv_rn(1.0f, fmaxf(d0, 1e-16f));
    float w1 = __fdiv_rn(1.0f, fmaxf(d1, 1e-16f));
    float w2 = __fdiv_rn(1.0f, fmaxf(d2b, 1e-16f));
    float s = __fadd_rn(__fadd_rn(w0, w1), w2);
    g_idx[3 * f + 0] = b * NC_PER + i0;
    g_idx[3 * f + 1] = b * NC_PER + i1;
    g_idx[3 * f + 2] = b * NC_PER + i2;
    g_w[4 * f + 0] = w0;
    g_w[4 * f + 1] = w1;
    g_w[4 * f + 2] = w2;
    g_w[4 * f + 3] = s;
}

// ---------------- Stage B: exact XLA-TopK emulation on flagged rows -------
struct KVT { float key; int idx; };
__device__ __forceinline__ bool kGt(const KVT& a, const KVT& b) { return a.key > b.key; }
__device__ __forceinline__ void cswap(KVT& x, KVT& y) {
    if (kGt(y, x)) { KVT t = x; x = y; y = t; }   // strict: ties never swap
}
__device__ __forceinline__ void sort4(KVT* a) {   // odd-even net, descending
    cswap(a[0], a[1]); cswap(a[2], a[3]);
    cswap(a[0], a[2]); cswap(a[1], a[3]);
    cswap(a[1], a[2]);
}
// bitonic top-4 merge of two descending 4-lists into a (prefer a on ties)
__device__ __forceinline__ void merge4(KVT* a, const KVT* b) {
    KVT m[4];
    #pragma unroll
    for (int i = 0; i < 4; i++) m[i] = kGt(b[3 - i], a[i]) ? b[3 - i] : a[i];
    cswap(m[0], m[2]); cswap(m[1], m[3]);         // bitonic cleanup
    cswap(m[0], m[1]); cswap(m[2], m[3]);
    #pragma unroll
    for (int i = 0; i < 4; i++) a[i] = m[i];
}
__device__ __forceinline__ void shfl_reduce(KVT* a, int lane) {
    for (int off = 16; off > 0; off >>= 1) {
        KVT bb[4];
        #pragma unroll
        for (int i = 0; i < 4; i++) {
            bb[i].key = __shfl_down_sync(0xffffffffu, a[i].key, off);
            bb[i].idx = __shfl_down_sync(0xffffffffu, a[i].idx, off);
        }
        if (lane < off) merge4(a, bb);
    }
}

__global__ void __launch_bounds__(1024) knn_exact_kernel(const float* __restrict__ pos,
                                                         const float* __restrict__ pos_skip) {
    __shared__ KVT s_lists[32][4];
    int tid = threadIdx.x, lane = tid & 31, warp = tid >> 5;
    int count = g_tiecount; if (count > 8192) count = 8192;

    for (int it = blockIdx.x; it < count; it += gridDim.x) {
        int f = g_tierows[it];
        int b = f >> 14;
        float qx = pos_skip[3 * f + 0];
        float qy = pos_skip[3 * f + 1];
        float qz = pos_skip[3 * f + 2];
        float qq = sq3(qx, qy, qz);
        const float* pb = pos + (size_t)b * NC_PER * 3;

        KVT a[4];
        #pragma unroll
        for (int i = 0; i < 4; i++) {
            int j = tid + (i << 10);              // strided: Idx(i)=1024*i+tid
            float px = pb[3 * j + 0], py = pb[3 * j + 1], pz = pb[3 * j + 2];
            float d2 = d2_chain(qx, qy, qz, qq, px, py, pz, sq3(px, py, pz));
            a[i].key = -d2;                        // top_k operates on -d2
            a[i].idx = j;
        }
        sort4(a);
        shfl_reduce(a, lane);                      // warp-level reduce
        if (lane == 0) {
            #pragma unroll
            for (int i = 0; i < 4; i++) s_lists[warp][i] = a[i];
        }
        __syncthreads();
        if (warp == 0) {
            KVT c[4];
            #pragma unroll
            for (int i = 0; i < 4; i++) c[i] = s_lists[lane][i];
            shfl_reduce(c, lane);                  // cross-warp reduce
            if (lane == 0) {
                float d0 = fmaxf(__fsub_rn(0.0f, c[0].key), 1e-16f);
                float d1 = fmaxf(__fsub_rn(0.0f, c[1].key), 1e-16f);
                float d2v = fmaxf(__fsub_rn(0.0f, c[2].key), 1e-16f);
                float w0 = __fdiv_rn(1.0f, d0);
                float w1 = __fdiv_rn(1.0f, d1);
                float w2 = __fdiv_rn(1.0f, d2v);
                float s = __fadd_rn(__fadd_rn(w0, w1), w2);
                g_idx[3 * f + 0] = b * NC_PER + c[0].idx;
                g_idx[3 * f + 1] = b * NC_PER + c[1].idx;
                g_idx[3 * f + 2] = b * NC_PER + c[2].idx;
                g_w[4 * f + 0] = w0;
                g_w[4 * f + 1] = w1;
                g_w[4 * f + 2] = w2;
                g_w[4 * f + 3] = s;
            }
        }
        __syncthreads();
    }
}

// ----- weighted gather: xi = ((w0*f0 + w1*f1) + w2*f2) / sum(w)  ----------
__global__ void __launch_bounds__(256) gather_kernel(const float* __restrict__ x) {
    int gid = blockIdx.x * 256 + threadIdx.x;
    int f  = gid >> 6;
    int c4 = (gid & 63) << 2;
    int j0 = g_idx[3 * f + 0], j1 = g_idx[3 * f + 1], j2 = g_idx[3 * f + 2];
    float w0 = g_w[4 * f + 0], w1 = g_w[4 * f + 1], w2 = g_w[4 * f + 2];
    float s  = g_w[4 * f + 3];
    float4 v0 = *(const float4*)(x + (size_t)j0 * 256 + c4);
    float4 v1 = *(const float4*)(x + (size_t)j1 * 256 + c4);
    float4 v2 = *(const float4*)(x + (size_t)j2 * 256 + c4);
    float4 o;
    o.x = __fdiv_rn(__fadd_rn(__fadd_rn(__fmul_rn(w0, v0.x), __fmul_rn(w1, v1.x)), __fmul_rn(w2, v2.x)), s);
    o.y = __fdiv_rn(__fadd_rn(__fadd_rn(__fmul_rn(w0, v0.y), __fmul_rn(w1, v1.y)), __fmul_rn(w2, v2.y)), s);
    o.z = __fdiv_rn(__fadd_rn(__fadd_rn(__fmul_rn(w0, v0.z), __fmul_rn(w1, v1.z)), __fmul_rn(w2, v2.z)), s);
    o.w = __fdiv_rn(__fadd_rn(__fadd_rn(__fmul_rn(w0, v0.w), __fmul_rn(w1, v1.w)), __fmul_rn(w2, v2.w)), s);
    *(float4*)(g_xi + (size_t)f * 256 + c4) = o;
}

// ---------------- fused fp32 GEMM + bias + ReLU ---------------------------
__global__ void __launch_bounds__(256) gemm_bias_relu(
    const float* __restrict__ Axtra,
    const float* __restrict__ Barg,
    const float* __restrict__ biasArg,
    float* __restrict__ Cout,
    int mode)
{
    __shared__ float As[16][128];
    __shared__ float Bs[16][64];
    __shared__ float sMu[256], sRsg[256], sBt[256];
    const int tid = threadIdx.x;
    const int m0 = blockIdx.x * 128;
    const int n0 = blockIdx.y * 64;
    const int tm = tid >> 4;
    const int tn = tid & 15;
    const int Ktot = mode ? K_TOT2 : K_TOT1;
    float* C = mode ? Cout : g_h1;

    if (mode) {
        sMu[tid]  = g_mu1[tid];
        sRsg[tid] = g_rsg1[tid];
        sBt[tid]  = Axtra[tid];       // beta1
    }
    __syncthreads();

    float acc[8][4];
    #pragma unroll
    for (int i = 0; i < 8; i++)
        #pragma unroll
        for (int j = 0; j < 4; j++) acc[i][j] = 0.f;

    const int ar = tid >> 2;
    const int ac = (tid & 3) << 2;
    const int bkr = tid >> 4;
    const int bc  = (tid & 15) << 2;

    for (int kk = 0; kk < Ktot; kk += 16) {
        const float* Asrc; int lda, kb;
        if (mode)          { Asrc = g_h1;  lda = 256; kb = kk; }
        else if (kk < 256) { Asrc = g_xi;  lda = 256; kb = kk; }
        else               { Asrc = Axtra; lda = 128; kb = kk - 256; }
        #pragma unroll
        for (int i = 0; i < 2; i++) {
            int r = ar + (i << 6);
            float4 v = *(const float4*)(Asrc + (size_t)(m0 + r) * lda + kb + ac);
            if (mode) {
                int k0 = kb + ac;
                v.x = __fadd_rn(__fmul_rn(__fsub_rn(v.x, sMu[k0 + 0]), sRsg[k0 + 0]), sBt[k0 + 0]);
                v.y = __fadd_rn(__fmul_rn(__fsub_rn(v.y, sMu[k0 + 1]), sRsg[k0 + 1]), sBt[k0 + 1]);
                v.z = __fadd_rn(__fmul_rn(__fsub_rn(v.z, sMu[k0 + 2]), sRsg[k0 + 2]), sBt[k0 + 2]);
                v.w = __fadd_rn(__fmul_rn(__fsub_rn(v.w, sMu[k0 + 3]), sRsg[k0 + 3]), sBt[k0 + 3]);
            }
            As[ac + 0][r] = v.x;
            As[ac + 1][r] = v.y;
            As[ac + 2][r] = v.z;
            As[ac + 3][r] = v.w;
        }
        *(float4*)(&Bs[bkr][bc]) =
            *(const float4*)(Barg + (size_t)(kk + bkr) * 256 + n0 + bc);
        __syncthreads();
        #pragma unroll
        for (int k = 0; k < 16; k++) {
            float4 bv = *(float4*)(&Bs[k][tn << 2]);
            float4 a0 = *(float4*)(&As[k][tm << 3]);
            float4 a1 = *(float4*)(&As[k][(tm << 3) + 4]);
            float a[8] = {a0.x, a0.y, a0.z, a0.w, a1.x, a1.y, a1.z, a1.w};
            float bb[4] = {bv.x, bv.y, bv.z, bv.w};
            #pragma unroll
            for (int i = 0; i < 8; i++)
                #pragma unroll
                for (int j = 0; j < 4; j++)
                    acc[i][j] = fmaf(a[i], bb[j], acc[i][j]);
        }
        __syncthreads();
    }

    float4 bb = *(const float4*)(biasArg + n0 + (tn << 2));
    #pragma unroll
    for (int i = 0; i < 8; i++) {
        float4 o;
        o.x = fmaxf(acc[i][0] + bb.x, 0.f);
        o.y = fmaxf(acc[i][1] + bb.y, 0.f);
        o.z = fmaxf(acc[i][2] + bb.z, 0.f);
        o.w = fmaxf(acc[i][3] + bb.w, 0.f);
        *(float4*)(C + (size_t)(m0 + (tm << 3) + i) * 256 + n0 + (tn << 2)) = o;
    }
}

// ---------------- deterministic column stats (sum, sumsq) -----------------
__global__ void __launch_bounds__(256) col_stats(const float* __restrict__ Aarg,
                                                 int which) {
    int c = threadIdx.x;
    const float* A = (which == 0) ? g_h1 : Aarg;
    const float* p = A + (size_t)blockIdx.x * 65536 + c;
    float s = 0.f, s2 = 0.f;
    #pragma unroll 8
    for (int r = 0; r < 256; r++) {
        float v = p[(size_t)r * 256];
        s  = __fadd_rn(s, v);
        s2 = __fmaf_rn(v, v, s2);
    }
    g_part[blockIdx.x * 512 + c]       = s;
    g_part[blockIdx.x * 512 + 256 + c] = s2;
}

__global__ void __launch_bounds__(256) finalize_bn(const float* __restrict__ g,
                                                   const float* __restrict__ beta,
                                                   int which) {
    int c = threadIdx.x;
    float s = 0.f, s2 = 0.f;
    #pragma unroll 8
    for (int b = 0; b < 256; b++) {
        s  += g_part[b * 512 + c];
        s2 += g_part[b * 512 + 256 + c];
    }
    float mu  = s * (1.0f / 65536.0f);
    float var = s2 * (1.0f / 65536.0f) - mu * mu;
    float rs  = 1.0f / sqrtf(var + 1e-5f);
    if (which == 0) {
        g_mu1[c]  = mu;
        g_rsg1[c] = g[c] * rs;
    } else {
        float sc = g[c] * rs;
        g_scale2[c] = sc;
        g_shift2[c] = beta[c] - mu * sc;
    }
}

// ---------------- final BN2 affine in-place on d_out ----------------------
__global__ void __launch_bounds__(256) affine_kernel(float* __restrict__ out) {
    int gid = blockIdx.x * 256 + threadIdx.x;
    int c4 = (gid & 63) << 2;
    float4 v = *(float4*)(out + (size_t)gid * 4);
    v.x = fmaf(v.x, g_scale2[c4 + 0], g_shift2[c4 + 0]);
    v.y = fmaf(v.y, g_scale2[c4 + 1], g_shift2[c4 + 1]);
    v.z = fmaf(v.z, g_scale2[c4 + 2], g_shift2[c4 + 2]);
    v.w = fmaf(v.w, g_scale2[c4 + 3], g_shift2[c4 + 3]);
    *(float4*)(out + (size_t)gid * 4) = v;
}

// ---------------- launch --------------------------------------------------
extern "C" void kernel_launch(void* const* d_in, const int* in_sizes, int n_in,
                              void* d_out, int out_size) {
    const float* x        = (const float*)d_in[0];
    const float* pos      = (const float*)d_in[1];
    const float* x_skip   = (const float*)d_in[2];
    const float* pos_skip = (const float*)d_in[3];
    const float* W1       = (const float*)d_in[4];
    const float* b1       = (const float*)d_in[5];
    const float* g1       = (const float*)d_in[6];
    const float* beta1    = (const float*)d_in[7];
    const float* W2       = (const float*)d_in[8];
    const float* b2       = (const float*)d_in[9];
    const float* g2       = (const float*)d_in[10];
    const float* beta2    = (const float*)d_in[11];
    float* out = (float*)d_out;

    reset_kernel<<<1, 1>>>();
    knn_kernel<<<512, 128>>>(pos, pos_skip);
    knn_exact_kernel<<<64, 1024>>>(pos, pos_skip);   // exact replay on ~17 rows
    gather_kernel<<<16384, 256>>>(x);

    dim3 gg(NF_TOT / 128, 256 / 64);
    gemm_bias_relu<<<gg, 256>>>(x_skip, W1, b1, out, 0);    // -> g_h1

    col_stats<<<256, 256>>>(out, 0);
    finalize_bn<<<1, 256>>>(g1, beta1, 0);

    gemm_bias_relu<<<gg, 256>>>(beta1, W2, b2, out, 1);     // -> d_out (pre-BN2)

    col_stats<<<256, 256>>>(out, 1);
    finalize_bn<<<1, 256>>>(g2, beta2, 1);
    affine_kernel<<<16384, 256>>>(out);
}

// round 13
// speedup vs baseline: 1.2409x; 1.2409x over previous
#include <cuda_runtime.h>
#include <cuda_bf16.h>
#include <math.h>
#include <stdint.h>

#define NC_PER 4096
#define NF_TOT 65536

// ---------------- device scratch (allocation-free contract) ----------------
__device__ __align__(16) float g_xi[(size_t)NF_TOT * 256];
__device__ __align__(16) float g_h1[(size_t)NF_TOT * 256];
__device__ int   g_idx[NF_TOT * 3];
__device__ float g_w[NF_TOT * 4];
__device__ float g_part[256 * 512];
__device__ float g_mu1[256], g_rsg1[256];
__device__ float g_scale2[256], g_shift2[256];
__device__ int   g_tiecount;
__device__ int   g_tierows[8192];
// W1^T and W2^T, bf16 split (hi, mid): [n][k]. W1t: 256x384 at 0, W2t: 256x256 at 98304
__device__ __align__(16) __nv_bfloat16 g_Bhi[256 * 384 + 256 * 256];
__device__ __align__(16) __nv_bfloat16 g_Bmid[256 * 384 + 256 * 256];

// ---------------- kNN numerics (bit-exact to reference, validated) --------
__device__ __forceinline__ float d2_chain(float qx, float qy, float qz, float qq,
                                          float px, float py, float pz, float pp) {
    float dot = __fadd_rn(__fadd_rn(__fmul_rn(qx, px), __fmul_rn(qy, py)),
                          __fmul_rn(qz, pz));
    return __fsub_rn(__fadd_rn(qq, pp), __fmul_rn(2.0f, dot));
}
__device__ __forceinline__ float sq3(float x, float y, float z) {
    return __fadd_rn(__fadd_rn(__fmul_rn(x, x), __fmul_rn(y, y)), __fmul_rn(z, z));
}

__global__ void reset_kernel() { g_tiecount = 0; }

// ---------------- Stage A: fast kNN + boundary-tie flagging ---------------
__global__ void __launch_bounds__(128) knn_kernel(const float* __restrict__ pos,
                                                  const float* __restrict__ pos_skip) {
    __shared__ float4 sp[2048];
    int f = blockIdx.x * 128 + threadIdx.x;
    int b = f >> 14;
    float qx = pos_skip[3 * f + 0];
    float qy = pos_skip[3 * f + 1];
    float qz = pos_skip[3 * f + 2];
    float qq = sq3(qx, qy, qz);
    float d0 = 3.4e38f, d1 = 3.4e38f, d2b = 3.4e38f, v3 = 3.4e38f;
    int i0 = 0, i1 = 0, i2 = 0;
    const float* pb = pos + (size_t)b * NC_PER * 3;

    for (int chunk = 0; chunk < 2; ++chunk) {
        __syncthreads();
        for (int i = threadIdx.x; i < 2048; i += 128) {
            int j = (chunk << 11) + i;
            float px = pb[3 * j + 0], py = pb[3 * j + 1], pz = pb[3 * j + 2];
            sp[i] = make_float4(px, py, pz, sq3(px, py, pz));
        }
        __syncthreads();
        #pragma unroll 4
        for (int i = 0; i < 2048; ++i) {
            float4 p = sp[i];
            float d2 = d2_chain(qx, qy, qz, qq, p.x, p.y, p.z, p.w);
            if (d2 < d2b) {
                int j = (chunk << 11) + i;
                v3 = d2b;
                if (d2 < d1) {
                    d2b = d1; i2 = i1;
                    if (d2 < d0) { d1 = d0; i1 = i0; d0 = d2; i0 = j; }
                    else         { d1 = d2; i1 = j; }
                } else { d2b = d2; i2 = j; }
            } else if (d2 < v3) {
                v3 = d2;
            }
        }
    }
    if (d2b == v3) {
        int slot = atomicAdd(&g_tiecount, 1);
        if (slot < 8192) g_tierows[slot] = f;
    }
    float w0 = __fdiv_rn(1.0f, fmaxf(d0, 1e-16f));
    float w1 = __fdiv_rn(1.0f, fmaxf(d1, 1e-16f));
    float w2 = __fdiv_rn(1.0f, fmaxf(d2b, 1e-16f));
    float s = __fadd_rn(__fadd_rn(w0, w1), w2);
    g_idx[3 * f + 0] = b * NC_PER + i0;
    g_idx[3 * f + 1] = b * NC_PER + i1;
    g_idx[3 * f + 2] = b * NC_PER + i2;
    g_w[4 * f + 0] = w0;
    g_w[4 * f + 1] = w1;
    g_w[4 * f + 2] = w2;
    g_w[4 * f + 3] = s;
}

// ---------------- Stage B: exact XLA-TopK emulation on flagged rows -------
struct KVT { float key; int idx; };
__device__ __forceinline__ bool kGt(const KVT& a, const KVT& b) { return a.key > b.key; }
__device__ __forceinline__ void cswap(KVT& x, KVT& y) {
    if (kGt(y, x)) { KVT t = x; x = y; y = t; }
}
__device__ __forceinline__ void sort4(KVT* a) {
    cswap(a[0], a[1]); cswap(a[2], a[3]);
    cswap(a[0], a[2]); cswap(a[1], a[3]);
    cswap(a[1], a[2]);
}
__device__ __forceinline__ void merge4(KVT* a, const KVT* b) {
    KVT m[4];
    #pragma unroll
    for (int i = 0; i < 4; i++) m[i] = kGt(b[3 - i], a[i]) ? b[3 - i] : a[i];
    cswap(m[0], m[2]); cswap(m[1], m[3]);
    cswap(m[0], m[1]); cswap(m[2], m[3]);
    #pragma unroll
    for (int i = 0; i < 4; i++) a[i] = m[i];
}
__device__ __forceinline__ void shfl_reduce(KVT* a, int lane) {
    for (int off = 16; off > 0; off >>= 1) {
        KVT bb[4];
        #pragma unroll
        for (int i = 0; i < 4; i++) {
            bb[i].key = __shfl_down_sync(0xffffffffu, a[i].key, off);
            bb[i].idx = __shfl_down_sync(0xffffffffu, a[i].idx, off);
        }
        if (lane < off) merge4(a, bb);
    }
}

__global__ void __launch_bounds__(1024) knn_exact_kernel(const float* __restrict__ pos,
                                                         const float* __restrict__ pos_skip) {
    __shared__ KVT s_lists[32][4];
    int tid = threadIdx.x, lane = tid & 31, warp = tid >> 5;
    int count = g_tiecount; if (count > 8192) count = 8192;

    for (int it = blockIdx.x; it < count; it += gridDim.x) {
        int f = g_tierows[it];
        int b = f >> 14;
        float qx = pos_skip[3 * f + 0];
        float qy = pos_skip[3 * f + 1];
        float qz = pos_skip[3 * f + 2];
        float qq = sq3(qx, qy, qz);
        const float* pb = pos + (size_t)b * NC_PER * 3;

        KVT a[4];
        #pragma unroll
        for (int i = 0; i < 4; i++) {
            int j = tid + (i << 10);
            float px = pb[3 * j + 0], py = pb[3 * j + 1], pz = pb[3 * j + 2];
            float d2 = d2_chain(qx, qy, qz, qq, px, py, pz, sq3(px, py, pz));
            a[i].key = -d2;
            a[i].idx = j;
        }
        sort4(a);
        shfl_reduce(a, lane);
        if (lane == 0) {
            #pragma unroll
            for (int i = 0; i < 4; i++) s_lists[warp][i] = a[i];
        }
        __syncthreads();
        if (warp == 0) {
            KVT c[4];
            #pragma unroll
            for (int i = 0; i < 4; i++) c[i] = s_lists[lane][i];
            shfl_reduce(c, lane);
            if (lane == 0) {
                float d0 = fmaxf(__fsub_rn(0.0f, c[0].key), 1e-16f);
                float d1 = fmaxf(__fsub_rn(0.0f, c[1].key), 1e-16f);
                float d2v = fmaxf(__fsub_rn(0.0f, c[2].key), 1e-16f);
                float w0 = __fdiv_rn(1.0f, d0);
                float w1 = __fdiv_rn(1.0f, d1);
                float w2 = __fdiv_rn(1.0f, d2v);
                float s = __fadd_rn(__fadd_rn(w0, w1), w2);
                g_idx[3 * f + 0] = b * NC_PER + c[0].idx;
                g_idx[3 * f + 1] = b * NC_PER + c[1].idx;
                g_idx[3 * f + 2] = b * NC_PER + c[2].idx;
                g_w[4 * f + 0] = w0;
                g_w[4 * f + 1] = w1;
                g_w[4 * f + 2] = w2;
                g_w[4 * f + 3] = s;
            }
        }
        __syncthreads();
    }
}

// ----- weighted gather (reference rounding, validated) --------------------
__global__ void __launch_bounds__(256) gather_kernel(const float* __restrict__ x) {
    int gid = blockIdx.x * 256 + threadIdx.x;
    int f  = gid >> 6;
    int c4 = (gid & 63) << 2;
    int j0 = g_idx[3 * f + 0], j1 = g_idx[3 * f + 1], j2 = g_idx[3 * f + 2];
    float w0 = g_w[4 * f + 0], w1 = g_w[4 * f + 1], w2 = g_w[4 * f + 2];
    float s  = g_w[4 * f + 3];
    float4 v0 = *(const float4*)(x + (size_t)j0 * 256 + c4);
    float4 v1 = *(const float4*)(x + (size_t)j1 * 256 + c4);
    float4 v2 = *(const float4*)(x + (size_t)j2 * 256 + c4);
    float4 o;
    o.x = __fdiv_rn(__fadd_rn(__fadd_rn(__fmul_rn(w0, v0.x), __fmul_rn(w1, v1.x)), __fmul_rn(w2, v2.x)), s);
    o.y = __fdiv_rn(__fadd_rn(__fadd_rn(__fmul_rn(w0, v0.y), __fmul_rn(w1, v1.y)), __fmul_rn(w2, v2.y)), s);
    o.z = __fdiv_rn(__fadd_rn(__fadd_rn(__fmul_rn(w0, v0.z), __fmul_rn(w1, v1.z)), __fmul_rn(w2, v2.z)), s);
    o.w = __fdiv_rn(__fadd_rn(__fadd_rn(__fmul_rn(w0, v0.w), __fmul_rn(w1, v1.w)), __fmul_rn(w2, v2.w)), s);
    *(float4*)(g_xi + (size_t)f * 256 + c4) = o;
}

// ----- prep: W^T bf16 split (hi/mid) once --------------------------------
__global__ void __launch_bounds__(256) prep_kernel(const float* __restrict__ W1,
                                                   const float* __restrict__ W2) {
    int idx = blockIdx.x * 256 + threadIdx.x;
    float w;
    if (idx < 98304) {
        int n = idx / 384, k = idx - n * 384;
        w = W1[k * 256 + n];
    } else {
        int j = idx - 98304;
        int n = j >> 8, k = j & 255;
        w = W2[k * 256 + n];
    }
    __nv_bfloat16 h = __float2bfloat16_rn(w);
    g_Bhi[idx]  = h;
    g_Bmid[idx] = __float2bfloat16_rn(__fsub_rn(w, __bfloat162float(h)));
}

// ---------------- mma.sync bf16x3 GEMM + bias + ReLU ----------------------
// CTA tile 128x128, BK=32, 8 warps (2m x 4n), warp tile 64x32.
// a*b ~= ah*bh + ah*bm + am*bh in fp32 accumulators (HMMA path).
#define SAPITCH 40   // bf16 elems per smem row (20 words: conflict-free, 16B-aligned)

__device__ __forceinline__ void mma_bf16(float* c, uint32_t a0, uint32_t a1,
                                         uint32_t a2, uint32_t a3,
                                         uint32_t b0, uint32_t b1) {
    asm volatile("mma.sync.aligned.m16n8k16.row.col.f32.bf16.bf16.f32 "
                 "{%0,%1,%2,%3}, {%4,%5,%6,%7}, {%8,%9}, {%0,%1,%2,%3};"
                 : "+f"(c[0]), "+f"(c[1]), "+f"(c[2]), "+f"(c[3])
                 : "r"(a0), "r"(a1), "r"(a2), "r"(a3), "r"(b0), "r"(b1));
}

__global__ void __launch_bounds__(256) gemm_mma(const float* __restrict__ Axtra,
                                                const float* __restrict__ bias,
                                                float* __restrict__ Cout,
                                                int mode) {
    __shared__ __nv_bfloat16 sAh[128 * SAPITCH], sAm[128 * SAPITCH];
    __shared__ __nv_bfloat16 sBh[128 * SAPITCH], sBm[128 * SAPITCH];
    __shared__ float bias_s[128], sMu[256], sRsg[256], sBt[256];

    const int tid = threadIdx.x;
    const int wid = tid >> 5, lane = tid & 31;
    const int warp_m = wid >> 2, warp_n = wid & 3;
    const int gid4 = lane >> 2, tid4 = lane & 3;
    const int m0 = blockIdx.x * 128;
    const int n0 = blockIdx.y * 128;
    const int nchunk = mode ? 8 : 12;
    const int Krow = mode ? 256 : 384;
    const int Boff = mode ? 98304 : 0;
    float* Cw = mode ? Cout : g_h1;

    if (tid < 128) bias_s[tid] = bias[n0 + tid];
    if (mode) { sMu[tid] = g_mu1[tid]; sRsg[tid] = g_rsg1[tid]; sBt[tid] = Axtra[tid]; }

    float acc[4][4][4];
    #pragma unroll
    for (int i = 0; i < 4; i++)
        #pragma unroll
        for (int j = 0; j < 4; j++)
            #pragma unroll
            for (int q = 0; q < 4; q++) acc[i][j][q] = 0.f;

    for (int ch = 0; ch < nchunk; ch++) {
        __syncthreads();
        // ---- A tile fill: 128 rows x 32 k, fp32 -> bf16 hi/mid -----------
        #pragma unroll
        for (int i = 0; i < 4; i++) {
            int idx = tid + (i << 8);          // 0..1023
            int row = idx >> 3;
            int k4  = (idx & 7) << 2;
            float4 v;
            if (mode) {
                v = *(const float4*)(g_h1 + (size_t)(m0 + row) * 256 + ch * 32 + k4);
                int k0 = ch * 32 + k4;
                v.x = __fadd_rn(__fmul_rn(__fsub_rn(v.x, sMu[k0 + 0]), sRsg[k0 + 0]), sBt[k0 + 0]);
                v.y = __fadd_rn(__fmul_rn(__fsub_rn(v.y, sMu[k0 + 1]), sRsg[k0 + 1]), sBt[k0 + 1]);
                v.z = __fadd_rn(__fmul_rn(__fsub_rn(v.z, sMu[k0 + 2]), sRsg[k0 + 2]), sBt[k0 + 2]);
                v.w = __fadd_rn(__fmul_rn(__fsub_rn(v.w, sMu[k0 + 3]), sRsg[k0 + 3]), sBt[k0 + 3]);
            } else if (ch < 8) {
                v = *(const float4*)(g_xi + (size_t)(m0 + row) * 256 + ch * 32 + k4);
            } else {
                v = *(const float4*)(Axtra + (size_t)(m0 + row) * 128 + (ch - 8) * 32 + k4);
            }
            __nv_bfloat16 h0 = __float2bfloat16_rn(v.x);
            __nv_bfloat16 h1 = __float2bfloat16_rn(v.y);
            __nv_bfloat16 h2 = __float2bfloat16_rn(v.z);
            __nv_bfloat16 h3 = __float2bfloat16_rn(v.w);
            __nv_bfloat16 l0 = __float2bfloat16_rn(__fsub_rn(v.x, __bfloat162float(h0)));
            __nv_bfloat16 l1 = __float2bfloat16_rn(__fsub_rn(v.y, __bfloat162float(h1)));
            __nv_bfloat16 l2 = __float2bfloat16_rn(__fsub_rn(v.z, __bfloat162float(h2)));
            __nv_bfloat16 l3 = __float2bfloat16_rn(__fsub_rn(v.w, __bfloat162float(h3)));
            uint32_t* ph = (uint32_t*)&sAh[row * SAPITCH + k4];
            uint32_t* pl = (uint32_t*)&sAm[row * SAPITCH + k4];
            ph[0] = ((uint32_t)__bfloat16_as_ushort(h1) << 16) | __bfloat16_as_ushort(h0);
            ph[1] = ((uint32_t)__bfloat16_as_ushort(h3) << 16) | __bfloat16_as_ushort(h2);
            pl[0] = ((uint32_t)__bfloat16_as_ushort(l1) << 16) | __bfloat16_as_ushort(l0);
            pl[1] = ((uint32_t)__bfloat16_as_ushort(l3) << 16) | __bfloat16_as_ushort(l2);
        }
        // ---- B tile fill: 128 n x 32 k bf16 (pre-split) ------------------
        #pragma unroll
        for (int i = 0; i < 2; i++) {
            int idx = tid + (i << 8);          // 0..511
            int n  = idx >> 2;
            int k8 = (idx & 3) << 3;
            size_t src = (size_t)Boff + (size_t)(n0 + n) * Krow + ch * 32 + k8;
            *(uint4*)&sBh[n * SAPITCH + k8] = *(const uint4*)(g_Bhi + src);
            *(uint4*)&sBm[n * SAPITCH + k8] = *(const uint4*)(g_Bmid + src);
        }
        __syncthreads();

        #pragma unroll
        for (int ks = 0; ks < 2; ks++) {
            int k0 = ks * 16 + tid4 * 2;
            uint32_t Ah[4][4], Am[4][4], Bh[4][2], Bm[4][2];
            #pragma unroll
            for (int mi = 0; mi < 4; mi++) {
                int r0 = (warp_m * 64 + mi * 16 + gid4) * SAPITCH;
                int r1 = r0 + 8 * SAPITCH;
                Ah[mi][0] = *(uint32_t*)&sAh[r0 + k0];
                Ah[mi][1] = *(uint32_t*)&sAh[r1 + k0];
                Ah[mi][2] = *(uint32_t*)&sAh[r0 + k0 + 8];
                Ah[mi][3] = *(uint32_t*)&sAh[r1 + k0 + 8];
                Am[mi][0] = *(uint32_t*)&sAm[r0 + k0];
                Am[mi][1] = *(uint32_t*)&sAm[r1 + k0];
                Am[mi][2] = *(uint32_t*)&sAm[r0 + k0 + 8];
                Am[mi][3] = *(uint32_t*)&sAm[r1 + k0 + 8];
            }
            #pragma unroll
            for (int ni = 0; ni < 4; ni++) {
                int c0 = (warp_n * 32 + ni * 8 + gid4) * SAPITCH;
                Bh[ni][0] = *(uint32_t*)&sBh[c0 + k0];
                Bh[ni][1] = *(uint32_t*)&sBh[c0 + k0 + 8];
                Bm[ni][0] = *(uint32_t*)&sBm[c0 + k0];
                Bm[ni][1] = *(uint32_t*)&sBm[c0 + k0 + 8];
            }
            #pragma unroll
            for (int mi = 0; mi < 4; mi++)
                #pragma unroll
                for (int ni = 0; ni < 4; ni++) {
                    mma_bf16(acc[mi][ni], Ah[mi][0], Ah[mi][1], Ah[mi][2], Ah[mi][3],
                             Bh[ni][0], Bh[ni][1]);
                    mma_bf16(acc[mi][ni], Ah[mi][0], Ah[mi][1], Ah[mi][2], Ah[mi][3],
                             Bm[ni][0], Bm[ni][1]);
                    mma_bf16(acc[mi][ni], Am[mi][0], Am[mi][1], Am[mi][2], Am[mi][3],
                             Bh[ni][0], Bh[ni][1]);
                }
        }
    }

    // ---- epilogue: bias + relu ------------------------------------------
    #pragma unroll
    for (int mi = 0; mi < 4; mi++) {
        int r0 = m0 + warp_m * 64 + mi * 16 + gid4;
        #pragma unroll
        for (int ni = 0; ni < 4; ni++) {
            int cl = warp_n * 32 + ni * 8 + tid4 * 2;   // col within CTA tile
            float b0 = bias_s[cl], b1 = bias_s[cl + 1];
            float2 o0, o1;
            o0.x = fmaxf(__fadd_rn(acc[mi][ni][0], b0), 0.f);
            o0.y = fmaxf(__fadd_rn(acc[mi][ni][1], b1), 0.f);
            o1.x = fmaxf(__fadd_rn(acc[mi][ni][2], b0), 0.f);
            o1.y = fmaxf(__fadd_rn(acc[mi][ni][3], b1), 0.f);
            *(float2*)(Cw + (size_t)r0 * 256 + n0 + cl) = o0;
            *(float2*)(Cw + (size_t)(r0 + 8) * 256 + n0 + cl) = o1;
        }
    }
}

// ---------------- deterministic column stats (sum, sumsq) -----------------
__global__ void __launch_bounds__(256) col_stats(const float* __restrict__ Aarg,
                                                 int which) {
    int c = threadIdx.x;
    const float* A = (which == 0) ? g_h1 : Aarg;
    const float* p = A + (size_t)blockIdx.x * 65536 + c;
    float s = 0.f, s2 = 0.f;
    #pragma unroll 8
    for (int r = 0; r < 256; r++) {
        float v = p[(size_t)r * 256];
        s  = __fadd_rn(s, v);
        s2 = __fmaf_rn(v, v, s2);
    }
    g_part[blockIdx.x * 512 + c]       = s;
    g_part[blockIdx.x * 512 + 256 + c] = s2;
}

__global__ void __launch_bounds__(256) finalize_bn(const float* __restrict__ g,
                                                   const float* __restrict__ beta,
                                                   int which) {
    int c = threadIdx.x;
    float s = 0.f, s2 = 0.f;
    #pragma unroll 8
    for (int b = 0; b < 256; b++) {
        s  += g_part[b * 512 + c];
        s2 += g_part[b * 512 + 256 + c];
    }
    float mu  = s * (1.0f / 65536.0f);
    float var = s2 * (1.0f / 65536.0f) - mu * mu;
    float rs  = 1.0f / sqrtf(var + 1e-5f);
    if (which == 0) {
        g_mu1[c]  = mu;
        g_rsg1[c] = g[c] * rs;
    } else {
        float sc = g[c] * rs;
        g_scale2[c] = sc;
        g_shift2[c] = beta[c] - mu * sc;
    }
}

// ---------------- final BN2 affine in-place on d_out ----------------------
__global__ void __launch_bounds__(256) affine_kernel(float* __restrict__ out) {
    int gid = blockIdx.x * 256 + threadIdx.x;
    int c4 = (gid & 63) << 2;
    float4 v = *(float4*)(out + (size_t)gid * 4);
    v.x = fmaf(v.x, g_scale2[c4 + 0], g_shift2[c4 + 0]);
    v.y = fmaf(v.y, g_scale2[c4 + 1], g_shift2[c4 + 1]);
    v.z = fmaf(v.z, g_scale2[c4 + 2], g_shift2[c4 + 2]);
    v.w = fmaf(v.w, g_scale2[c4 + 3], g_shift2[c4 + 3]);
    *(float4*)(out + (size_t)gid * 4) = v;
}

// ---------------- launch --------------------------------------------------
extern "C" void kernel_launch(void* const* d_in, const int* in_sizes, int n_in,
                              void* d_out, int out_size) {
    const float* x        = (const float*)d_in[0];
    const float* pos      = (const float*)d_in[1];
    const float* x_skip   = (const float*)d_in[2];
    const float* pos_skip = (const float*)d_in[3];
    const float* W1       = (const float*)d_in[4];
    const float* b1       = (const float*)d_in[5];
    const float* g1       = (const float*)d_in[6];
    const float* beta1    = (const float*)d_in[7];
    const float* W2       = (const float*)d_in[8];
    const float* b2       = (const float*)d_in[9];
    const float* g2       = (const float*)d_in[10];
    const float* beta2    = (const float*)d_in[11];
    float* out = (float*)d_out;

    reset_kernel<<<1, 1>>>();
    knn_kernel<<<512, 128>>>(pos, pos_skip);
    knn_exact_kernel<<<64, 1024>>>(pos, pos_skip);
    gather_kernel<<<16384, 256>>>(x);
    prep_kernel<<<640, 256>>>(W1, W2);

    dim3 gg(NF_TOT / 128, 2);
    gemm_mma<<<gg, 256>>>(x_skip, b1, nullptr, 0);   // -> g_h1

    col_stats<<<256, 256>>>(out, 0);
    finalize_bn<<<1, 256>>>(g1, beta1, 0);

    gemm_mma<<<gg, 256>>>(beta1, b2, out, 1);        // -> d_out

    col_stats<<<256, 256>>>(out, 1);
    finalize_bn<<<1, 256>>>(g2, beta2, 1);
    affine_kernel<<<16384, 256>>>(out);
}

// round 17
// speedup vs baseline: 1.2659x; 1.0202x over previous
#include <cuda_runtime.h>
#include <cuda_bf16.h>
#include <math.h>
#include <stdint.h>

#define NC_PER 4096
#define NF_TOT 65536

// ---------------- device scratch (allocation-free contract) ----------------
__device__ __align__(16) float g_h1[(size_t)NF_TOT * 256];
__device__ int   g_idx[NF_TOT * 3];
__device__ float g_w[NF_TOT * 4];
__device__ float g_part[256 * 512];
__device__ float g_mu1[256], g_rsg1[256];
__device__ float g_scale2[256], g_shift2[256];
__device__ int   g_tiecount;
__device__ int   g_tierows[8192];
// GEMM operands, all pre-split bf16 (hi, mid):
// A1 = [xi | x_skip]: [65536][384]; A2 = bn1(h1): [65536][256]
__device__ __align__(16) __nv_bfloat16 g_A1hi[(size_t)NF_TOT * 384];
__device__ __align__(16) __nv_bfloat16 g_A1mid[(size_t)NF_TOT * 384];
__device__ __align__(16) __nv_bfloat16 g_A2hi[(size_t)NF_TOT * 256];
__device__ __align__(16) __nv_bfloat16 g_A2mid[(size_t)NF_TOT * 256];
// W1^T [256][384] at 0, W2^T [256][256] at 98304
__device__ __align__(16) __nv_bfloat16 g_Bhi[256 * 384 + 256 * 256];
__device__ __align__(16) __nv_bfloat16 g_Bmid[256 * 384 + 256 * 256];

// ---------------- helpers --------------------------------------------------
__device__ __forceinline__ float d2_chain(float qx, float qy, float qz, float qq,
                                          float px, float py, float pz, float pp) {
    float dot = __fadd_rn(__fadd_rn(__fmul_rn(qx, px), __fmul_rn(qy, py)),
                          __fmul_rn(qz, pz));
    return __fsub_rn(__fadd_rn(qq, pp), __fmul_rn(2.0f, dot));
}
__device__ __forceinline__ float sq3(float x, float y, float z) {
    return __fadd_rn(__fadd_rn(__fmul_rn(x, x), __fmul_rn(y, y)), __fmul_rn(z, z));
}
__device__ __forceinline__ void split_bf16(float v, __nv_bfloat16& h, __nv_bfloat16& m) {
    h = __float2bfloat16_rn(v);
    m = __float2bfloat16_rn(__fsub_rn(v, __bfloat162float(h)));
}

__global__ void reset_kernel() { g_tiecount = 0; }

// ---------------- Stage A: fast kNN (FFMA screen + exact slow path) -------
__global__ void __launch_bounds__(128) knn_kernel(const float* __restrict__ pos,
                                                  const float* __restrict__ pos_skip) {
    __shared__ float4 sp[2048];       // (px,py,pz, 0.5*pp)
    int f = blockIdx.x * 128 + threadIdx.x;
    int b = f >> 14;
    float qx = pos_skip[3 * f + 0];
    float qy = pos_skip[3 * f + 1];
    float qz = pos_skip[3 * f + 2];
    float qq = sq3(qx, qy, qz);
    float nqx = -qx, nqy = -qy, nqz = -qz;
    float d0 = 3.4e38f, d1 = 3.4e38f, d2b = 3.4e38f, v3 = 3.4e38f;
    float tv = 3.4e38f;               // t-space screen threshold (covers v3)
    int i0 = 0, i1 = 0, i2 = 0;
    const float* pb = pos + (size_t)b * NC_PER * 3;

    for (int chunk = 0; chunk < 2; ++chunk) {
        __syncthreads();
        for (int i = threadIdx.x; i < 2048; i += 128) {
            int j = (chunk << 11) + i;
            float px = pb[3 * j + 0], py = pb[3 * j + 1], pz = pb[3 * j + 2];
            sp[i] = make_float4(px, py, pz, 0.5f * sq3(px, py, pz));
        }
        __syncthreads();
        #pragma unroll 8
        for (int i = 0; i < 2048; ++i) {
            float4 p = sp[i];
            // fast screen: t ~ 0.5*pp - q.p ; within ~5e-7 of exact chain
            float t = __fmaf_rn(nqx, p.x, __fmaf_rn(nqy, p.y, __fmaf_rn(nqz, p.z, p.w)));
            if (t < tv) {
                float pp = __fmul_rn(2.0f, p.w);      // exact pp recovery
                float d2 = d2_chain(qx, qy, qz, qq, p.x, p.y, p.z, pp);
                if (d2 < d2b) {
                    int j = (chunk << 11) + i;
                    v3 = d2b;
                    if (d2 < d1) {
                        d2b = d1; i2 = i1;
                        if (d2 < d0) { d1 = d0; i1 = i0; d0 = d2; i0 = j; }
                        else         { d1 = d2; i1 = j; }
                    } else { d2b = d2; i2 = j; }
                } else if (d2 < v3) {
                    v3 = d2;
                }
                tv = 0.5f * (v3 - qq) + 2e-5f;        // margin >> fma deviation
            }
        }
    }
    if (d2b == v3) {
        int slot = atomicAdd(&g_tiecount, 1);
        if (slot < 8192) g_tierows[slot] = f;
    }
    float w0 = __fdiv_rn(1.0f, fmaxf(d0, 1e-16f));
    float w1 = __fdiv_rn(1.0f, fmaxf(d1, 1e-16f));
    float w2 = __fdiv_rn(1.0f, fmaxf(d2b, 1e-16f));
    float s = __fadd_rn(__fadd_rn(w0, w1), w2);
    g_idx[3 * f + 0] = b * NC_PER + i0;
    g_idx[3 * f + 1] = b * NC_PER + i1;
    g_idx[3 * f + 2] = b * NC_PER + i2;
    g_w[4 * f + 0] = w0;
    g_w[4 * f + 1] = w1;
    g_w[4 * f + 2] = w2;
    g_w[4 * f + 3] = s;
}

// ---------------- Stage B: exact XLA-TopK emulation on flagged rows -------
struct KVT { float key; int idx; };
__device__ __forceinline__ bool kGt(const KVT& a, const KVT& b) { return a.key > b.key; }
__device__ __forceinline__ void cswap(KVT& x, KVT& y) {
    if (kGt(y, x)) { KVT t = x; x = y; y = t; }
}
__device__ __forceinline__ void sort4(KVT* a) {
    cswap(a[0], a[1]); cswap(a[2], a[3]);
    cswap(a[0], a[2]); cswap(a[1], a[3]);
    cswap(a[1], a[2]);
}
__device__ __forceinline__ void merge4(KVT* a, const KVT* b) {
    KVT m[4];
    #pragma unroll
    for (int i = 0; i < 4; i++) m[i] = kGt(b[3 - i], a[i]) ? b[3 - i] : a[i];
    cswap(m[0], m[2]); cswap(m[1], m[3]);
    cswap(m[0], m[1]); cswap(m[2], m[3]);
    #pragma unroll
    for (int i = 0; i < 4; i++) a[i] = m[i];
}
__device__ __forceinline__ void shfl_reduce(KVT* a, int lane) {
    for (int off = 16; off > 0; off >>= 1) {
        KVT bb[4];
        #pragma unroll
        for (int i = 0; i < 4; i++) {
            bb[i].key = __shfl_down_sync(0xffffffffu, a[i].key, off);
            bb[i].idx = __shfl_down_sync(0xffffffffu, a[i].idx, off);
        }
        if (lane < off) merge4(a, bb);
    }
}

__global__ void __launch_bounds__(1024) knn_exact_kernel(const float* __restrict__ pos,
                                                         const float* __restrict__ pos_skip) {
    __shared__ KVT s_lists[32][4];
    int tid = threadIdx.x, lane = tid & 31, warp = tid >> 5;
    int count = g_tiecount; if (count > 8192) count = 8192;

    for (int it = blockIdx.x; it < count; it += gridDim.x) {
        int f = g_tierows[it];
        int b = f >> 14;
        float qx = pos_skip[3 * f + 0];
        float qy = pos_skip[3 * f + 1];
        float qz = pos_skip[3 * f + 2];
        float qq = sq3(qx, qy, qz);
        const float* pb = pos + (size_t)b * NC_PER * 3;

        KVT a[4];
        #pragma unroll
        for (int i = 0; i < 4; i++) {
            int j = tid + (i << 10);
            float px = pb[3 * j + 0], py = pb[3 * j + 1], pz = pb[3 * j + 2];
            float d2 = d2_chain(qx, qy, qz, qq, px, py, pz, sq3(px, py, pz));
            a[i].key = -d2;
            a[i].idx = j;
        }
        sort4(a);
        shfl_reduce(a, lane);
        if (lane == 0) {
            #pragma unroll
            for (int i = 0; i < 4; i++) s_lists[warp][i] = a[i];
        }
        __syncthreads();
        if (warp == 0) {
            KVT c[4];
            #pragma unroll
            for (int i = 0; i < 4; i++) c[i] = s_lists[lane][i];
            shfl_reduce(c, lane);
            if (lane == 0) {
                float d0 = fmaxf(__fsub_rn(0.0f, c[0].key), 1e-16f);
                float d1 = fmaxf(__fsub_rn(0.0f, c[1].key), 1e-16f);
                float d2v = fmaxf(__fsub_rn(0.0f, c[2].key), 1e-16f);
                float w0 = __fdiv_rn(1.0f, d0);
                float w1 = __fdiv_rn(1.0f, d1);
                float w2 = __fdiv_rn(1.0f, d2v);
                float s = __fadd_rn(__fadd_rn(w0, w1), w2);
                g_idx[3 * f + 0] = b * NC_PER + c[0].idx;
                g_idx[3 * f + 1] = b * NC_PER + c[1].idx;
                g_idx[3 * f + 2] = b * NC_PER + c[2].idx;
                g_w[4 * f + 0] = w0;
                g_w[4 * f + 1] = w1;
                g_w[4 * f + 2] = w2;
                g_w[4 * f + 3] = s;
            }
        }
        __syncthreads();
    }
}

// ----- gather: reference-rounded xi, written directly as split bf16 -------
__global__ void __launch_bounds__(256) gather_kernel(const float* __restrict__ x) {
    int gid = blockIdx.x * 256 + threadIdx.x;
    int f  = gid >> 6;
    int c4 = (gid & 63) << 2;
    int j0 = g_idx[3 * f + 0], j1 = g_idx[3 * f + 1], j2 = g_idx[3 * f + 2];
    float w0 = g_w[4 * f + 0], w1 = g_w[4 * f + 1], w2 = g_w[4 * f + 2];
    float s  = g_w[4 * f + 3];
    float4 v0 = *(const float4*)(x + (size_t)j0 * 256 + c4);
    float4 v1 = *(const float4*)(x + (size_t)j1 * 256 + c4);
    float4 v2 = *(const float4*)(x + (size_t)j2 * 256 + c4);
    float4 o;
    o.x = __fdiv_rn(__fadd_rn(__fadd_rn(__fmul_rn(w0, v0.x), __fmul_rn(w1, v1.x)), __fmul_rn(w2, v2.x)), s);
    o.y = __fdiv_rn(__fadd_rn(__fadd_rn(__fmul_rn(w0, v0.y), __fmul_rn(w1, v1.y)), __fmul_rn(w2, v2.y)), s);
    o.z = __fdiv_rn(__fadd_rn(__fadd_rn(__fmul_rn(w0, v0.z), __fmul_rn(w1, v1.z)), __fmul_rn(w2, v2.z)), s);
    o.w = __fdiv_rn(__fadd_rn(__fadd_rn(__fmul_rn(w0, v0.w), __fmul_rn(w1, v1.w)), __fmul_rn(w2, v2.w)), s);
    __nv_bfloat16 h[4], m[4];
    split_bf16(o.x, h[0], m[0]); split_bf16(o.y, h[1], m[1]);
    split_bf16(o.z, h[2], m[2]); split_bf16(o.w, h[3], m[3]);
    size_t dst = (size_t)f * 384 + c4;
    *(uint2*)(g_A1hi + dst)  = *(uint2*)h;
    *(uint2*)(g_A1mid + dst) = *(uint2*)m;
}

// ----- split x_skip into A1 cols 256..383 ---------------------------------
__global__ void __launch_bounds__(256) split_xskip(const float* __restrict__ xs) {
    int gid = blockIdx.x * 256 + threadIdx.x;   // 65536*32 float4 lanes
    int f  = gid >> 5;
    int c4 = (gid & 31) << 2;
    float4 v = *(const float4*)(xs + (size_t)f * 128 + c4);
    __nv_bfloat16 h[4], m[4];
    split_bf16(v.x, h[0], m[0]); split_bf16(v.y, h[1], m[1]);
    split_bf16(v.z, h[2], m[2]); split_bf16(v.w, h[3], m[3]);
    size_t dst = (size_t)f * 384 + 256 + c4;
    *(uint2*)(g_A1hi + dst)  = *(uint2*)h;
    *(uint2*)(g_A1mid + dst) = *(uint2*)m;
}

// ----- prep: W^T bf16 split (hi/mid) once ---------------------------------
__global__ void __launch_bounds__(256) prep_kernel(const float* __restrict__ W1,
                                                   const float* __restrict__ W2) {
    int idx = blockIdx.x * 256 + threadIdx.x;
    float w;
    if (idx < 98304) {
        int n = idx / 384, k = idx - n * 384;
        w = W1[k * 256 + n];
    } else {
        int j = idx - 98304;
        int n = j >> 8, k = j & 255;
        w = W2[k * 256 + n];
    }
    __nv_bfloat16 h, m;
    split_bf16(w, h, m);
    g_Bhi[idx]  = h;
    g_Bmid[idx] = m;
}

// ----- bn_split: A2 = bn1(g_h1), reference-order chain, split bf16 --------
__global__ void __launch_bounds__(256) bn_split(const float* __restrict__ beta1) {
    int gid = blockIdx.x * 256 + threadIdx.x;   // 65536*64 float4 lanes
    int f  = gid >> 6;
    int c4 = (gid & 63) << 2;
    float4 v = *(const float4*)(g_h1 + (size_t)f * 256 + c4);
    v.x = __fadd_rn(__fmul_rn(__fsub_rn(v.x, g_mu1[c4 + 0]), g_rsg1[c4 + 0]), beta1[c4 + 0]);
    v.y = __fadd_rn(__fmul_rn(__fsub_rn(v.y, g_mu1[c4 + 1]), g_rsg1[c4 + 1]), beta1[c4 + 1]);
    v.z = __fadd_rn(__fmul_rn(__fsub_rn(v.z, g_mu1[c4 + 2]), g_rsg1[c4 + 2]), beta1[c4 + 2]);
    v.w = __fadd_rn(__fmul_rn(__fsub_rn(v.w, g_mu1[c4 + 3]), g_rsg1[c4 + 3]), beta1[c4 + 3]);
    __nv_bfloat16 h[4], m[4];
    split_bf16(v.x, h[0], m[0]); split_bf16(v.y, h[1], m[1]);
    split_bf16(v.z, h[2], m[2]); split_bf16(v.w, h[3], m[3]);
    size_t dst = (size_t)f * 256 + c4;
    *(uint2*)(g_A2hi + dst)  = *(uint2*)h;
    *(uint2*)(g_A2mid + dst) = *(uint2*)m;
}

// ---------------- mma.sync bf16x3 GEMM (R13 skeleton, pre-split input) ----
// CTA tile 128x128, BK=32, 8 warps (2m x 4n), warp tile 64x32.
// Static smem, synchronous LDG.128 -> STS.128 fills.
// mode 0: A = g_A1* (K=384), B at 0,  C = g_h1
// mode 1: A = g_A2* (K=256), B at 98304, C = Cout (d_out)
// NOTE: device globals are resolved INSIDE the kernel (host cannot take
// the address of __device__ symbols — that was the R15/R16 bug).
#define SAPITCH 40   // bf16 per smem row (20 words: conflict-free, 16B-aligned)

__device__ __forceinline__ void mma_bf16(float* c, uint32_t a0, uint32_t a1,
                                         uint32_t a2, uint32_t a3,
                                         uint32_t b0, uint32_t b1) {
    asm volatile("mma.sync.aligned.m16n8k16.row.col.f32.bf16.bf16.f32 "
                 "{%0,%1,%2,%3}, {%4,%5,%6,%7}, {%8,%9}, {%0,%1,%2,%3};"
                 : "+f"(c[0]), "+f"(c[1]), "+f"(c[2]), "+f"(c[3])
                 : "r"(a0), "r"(a1), "r"(a2), "r"(a3), "r"(b0), "r"(b1));
}

__global__ void __launch_bounds__(256) gemm_mma(const float* __restrict__ bias,
                                                float* __restrict__ Cout,
                                                int mode) {
    __shared__ __nv_bfloat16 sAh[128 * SAPITCH], sAm[128 * SAPITCH];
    __shared__ __nv_bfloat16 sBh[128 * SAPITCH], sBm[128 * SAPITCH];
    __shared__ float bias_s[128];

    const int tid = threadIdx.x;
    const int wid = tid >> 5, lane = tid & 31;
    const int warp_m = wid >> 2, warp_n = wid & 3;
    const int gid4 = lane >> 2, tid4 = lane & 3;
    const int m0 = blockIdx.x * 128;
    const int n0 = blockIdx.y * 128;
    const int Krow = mode ? 256 : 384;
    const int Boff = mode ? 98304 : 0;
    const int nchunk = Krow >> 5;
    const __nv_bfloat16* Ahi = mode ? g_A2hi  : g_A1hi;
    const __nv_bfloat16* Ami = mode ? g_A2mid : g_A1mid;
    float* Cw = mode ? Cout : g_h1;

    if (tid < 128) bias_s[tid] = bias[n0 + tid];

    float acc[4][4][4];
    #pragma unroll
    for (int i = 0; i < 4; i++)
        #pragma unroll
        for (int j = 0; j < 4; j++)
            #pragma unroll
            for (int q = 0; q < 4; q++) acc[i][j][q] = 0.f;

    for (int ch = 0; ch < nchunk; ch++) {
        __syncthreads();
        // fills: 512 cids cover 128 rows x 4 segs of 8 bf16 (16B)
        #pragma unroll
        for (int j = 0; j < 2; j++) {
            int cid = tid + (j << 8);
            int row = cid >> 2, seg = cid & 3;
            int doff = row * SAPITCH + seg * 8;
            size_t asrc = (size_t)(m0 + row) * Krow + ch * 32 + seg * 8;
            *(uint4*)&sAh[doff] = *(const uint4*)(Ahi + asrc);
            *(uint4*)&sAm[doff] = *(const uint4*)(Ami + asrc);
            size_t bsrc = (size_t)Boff + (size_t)(n0 + row) * Krow + ch * 32 + seg * 8;
            *(uint4*)&sBh[doff] = *(const uint4*)(g_Bhi + bsrc);
            *(uint4*)&sBm[doff] = *(const uint4*)(g_Bmid + bsrc);
        }
        __syncthreads();

        #pragma unroll
        for (int ks = 0; ks < 2; ks++) {
            int k0 = ks * 16 + tid4 * 2;
            uint32_t Ah[4][4], Am[4][4], Bh[4][2], Bm[4][2];
            #pragma unroll
            for (int mi = 0; mi < 4; mi++) {
                int r0 = (warp_m * 64 + mi * 16 + gid4) * SAPITCH;
                int r1 = r0 + 8 * SAPITCH;
                Ah[mi][0] = *(uint32_t*)&sAh[r0 + k0];
                Ah[mi][1] = *(uint32_t*)&sAh[r1 + k0];
                Ah[mi][2] = *(uint32_t*)&sAh[r0 + k0 + 8];
                Ah[mi][3] = *(uint32_t*)&sAh[r1 + k0 + 8];
                Am[mi][0] = *(uint32_t*)&sAm[r0 + k0];
                Am[mi][1] = *(uint32_t*)&sAm[r1 + k0];
                Am[mi][2] = *(uint32_t*)&sAm[r0 + k0 + 8];
                Am[mi][3] = *(uint32_t*)&sAm[r1 + k0 + 8];
            }
            #pragma unroll
            for (int ni = 0; ni < 4; ni++) {
                int c0 = (warp_n * 32 + ni * 8 + gid4) * SAPITCH;
                Bh[ni][0] = *(uint32_t*)&sBh[c0 + k0];
                Bh[ni][1] = *(uint32_t*)&sBh[c0 + k0 + 8];
                Bm[ni][0] = *(uint32_t*)&sBm[c0 + k0];
                Bm[ni][1] = *(uint32_t*)&sBm[c0 + k0 + 8];
            }
            #pragma unroll
            for (int mi = 0; mi < 4; mi++)
                #pragma unroll
                for (int ni = 0; ni < 4; ni++) {
                    mma_bf16(acc[mi][ni], Ah[mi][0], Ah[mi][1], Ah[mi][2], Ah[mi][3],
                             Bh[ni][0], Bh[ni][1]);
                    mma_bf16(acc[mi][ni], Ah[mi][0], Ah[mi][1], Ah[mi][2], Ah[mi][3],
                             Bm[ni][0], Bm[ni][1]);
                    mma_bf16(acc[mi][ni], Am[mi][0], Am[mi][1], Am[mi][2], Am[mi][3],
                             Bh[ni][0], Bh[ni][1]);
                }
        }
    }

    // ---- epilogue: bias + relu ------------------------------------------
    #pragma unroll
    for (int mi = 0; mi < 4; mi++) {
        int r0 = m0 + warp_m * 64 + mi * 16 + gid4;
        #pragma unroll
        for (int ni = 0; ni < 4; ni++) {
            int cl = warp_n * 32 + ni * 8 + tid4 * 2;
            float b0 = bias_s[cl], b1 = bias_s[cl + 1];
            float2 o0, o1;
            o0.x = fmaxf(__fadd_rn(acc[mi][ni][0], b0), 0.f);
            o0.y = fmaxf(__fadd_rn(acc[mi][ni][1], b1), 0.f);
            o1.x = fmaxf(__fadd_rn(acc[mi][ni][2], b0), 0.f);
            o1.y = fmaxf(__fadd_rn(acc[mi][ni][3], b1), 0.f);
            *(float2*)(Cw + (size_t)r0 * 256 + n0 + cl) = o0;
            *(float2*)(Cw + (size_t)(r0 + 8) * 256 + n0 + cl) = o1;
        }
    }
}

// ---------------- deterministic column stats (sum, sumsq) -----------------
__global__ void __launch_bounds__(256) col_stats(const float* __restrict__ Aarg,
                                                 int which) {
    int c = threadIdx.x;
    const float* A = (which == 0) ? g_h1 : Aarg;
    const float* p = A + (size_t)blockIdx.x * 65536 + c;
    float s = 0.f, s2 = 0.f;
    #pragma unroll 8
    for (int r = 0; r < 256; r++) {
        float v = p[(size_t)r * 256];
        s  = __fadd_rn(s, v);
        s2 = __fmaf_rn(v, v, s2);
    }
    g_part[blockIdx.x * 512 + c]       = s;
    g_part[blockIdx.x * 512 + 256 + c] = s2;
}

__global__ void __launch_bounds__(256) finalize_bn(const float* __restrict__ g,
                                                   const float* __restrict__ beta,
                                                   int which) {
    int c = threadIdx.x;
    float s = 0.f, s2 = 0.f;
    #pragma unroll 8
    for (int b = 0; b < 256; b++) {
        s  += g_part[b * 512 + c];
        s2 += g_part[b * 512 + 256 + c];
    }
    float mu  = s * (1.0f / 65536.0f);
    float var = s2 * (1.0f / 65536.0f) - mu * mu;
    float rs  = 1.0f / sqrtf(var + 1e-5f);
    if (which == 0) {
        g_mu1[c]  = mu;
        g_rsg1[c] = g[c] * rs;
    } else {
        float sc = g[c] * rs;
        g_scale2[c] = sc;
        g_shift2[c] = beta[c] - mu * sc;
    }
}

// ---------------- final BN2 affine in-place on d_out ----------------------
__global__ void __launch_bounds__(256) affine_kernel(float* __restrict__ out) {
    int gid = blockIdx.x * 256 + threadIdx.x;
    int c4 = (gid & 63) << 2;
    float4 v = *(float4*)(out + (size_t)gid * 4);
    v.x = fmaf(v.x, g_scale2[c4 + 0], g_shift2[c4 + 0]);
    v.y = fmaf(v.y, g_scale2[c4 + 1], g_shift2[c4 + 1]);
    v.z = fmaf(v.z, g_scale2[c4 + 2], g_shift2[c4 + 2]);
    v.w = fmaf(v.w, g_scale2[c4 + 3], g_shift2[c4 + 3]);
    *(float4*)(out + (size_t)gid * 4) = v;
}

// ---------------- launch --------------------------------------------------
extern "C" void kernel_launch(void* const* d_in, const int* in_sizes, int n_in,
                              void* d_out, int out_size) {
    const float* x        = (const float*)d_in[0];
    const float* pos      = (const float*)d_in[1];
    const float* x_skip   = (const float*)d_in[2];
    const float* pos_skip = (const float*)d_in[3];
    const float* W1       = (const float*)d_in[4];
    const float* b1       = (const float*)d_in[5];
    const float* g1       = (const float*)d_in[6];
    const float* beta1    = (const float*)d_in[7];
    const float* W2       = (const float*)d_in[8];
    const float* b2       = (const float*)d_in[9];
    const float* g2       = (const float*)d_in[10];
    const float* beta2    = (const float*)d_in[11];
    float* out = (float*)d_out;

    reset_kernel<<<1, 1>>>();
    knn_kernel<<<512, 128>>>(pos, pos_skip);
    knn_exact_kernel<<<64, 1024>>>(pos, pos_skip);
    gather_kernel<<<16384, 256>>>(x);
    split_xskip<<<8192, 256>>>(x_skip);
    prep_kernel<<<640, 256>>>(W1, W2);

    dim3 gg(NF_TOT / 128, 2);
    gemm_mma<<<gg, 256>>>(b1, nullptr, 0);   // -> g_h1

    col_stats<<<256, 256>>>(out, 0);
    finalize_bn<<<1, 256>>>(g1, beta1, 0);
    bn_split<<<16384, 256>>>(beta1);

    gemm_mma<<<gg, 256>>>(b2, out, 1);       // -> d_out

    col_stats<<<256, 256>>>(out, 1);
    finalize_bn<<<1, 256>>>(g2, beta2, 1);
    affine_kernel<<<16384, 256>>>(out);
}